// round 1
// baseline (speedup 1.0000x reference)
#include <cuda_runtime.h>
#include <cstdint>

// Problem constants
#define B__ 8192
#define O__ 8
#define N__ 8
#define U__ 256
#define K__ 2048   // N__*U__
#define V__ 256

// GEMM tiling
#define BM 128
#define BN 128
#define BK 32
#define AS_LD 36    // pad: bank = (4m+k)%32, conflict-free frag loads
#define BS_LD 136   // pad: bank = (8k+c)%32, conflict-free frag loads

// 16 MB scratch: gated + tf32-rounded weights W[o][k][v]
__device__ float g_w[(size_t)O__ * K__ * V__];

__device__ __forceinline__ uint32_t tf32r(float x) {
    uint32_t u;
    asm("cvt.rna.tf32.f32 %0, %1;" : "=r"(u) : "f"(x));
    return u;
}

// ---------------------------------------------------------------------------
// Kernel 1: compute hard-concrete gate z[o,n] and write W[o][k][v] = T*z,
// pre-rounded to tf32 (round-to-nearest kills truncation bias in the MMA).
// 1,048,576 float4s over 4096 blocks x 256 threads.
// ---------------------------------------------------------------------------
__global__ void gate_scale_kernel(const float* __restrict__ T,
                                  const float* __restrict__ alpha,
                                  const float* __restrict__ u_param) {
    __shared__ float zsh[64];
    int t = threadIdx.x;
    if (t < 64) {
        float uu = u_param[t];
        float s = logf(uu) - logf(1.0f - uu) + logf(alpha[0]) / 0.9f;
        s = 1.0f / (1.0f + expf(-s));
        float z = s * 1.2f - 0.1f;               // s*(EPSILON-GAMMA)+GAMMA
        zsh[t] = fminf(fmaxf(z, 0.0f), 1.0f);
    }
    __syncthreads();

    int i = blockIdx.x * 256 + t;                // float4 index
    int fl = i << 2;                             // element index (< 2^22)
    int o = fl >> 19;                            // / (2048*256)
    int n = (fl >> 16) & 7;                      // / (256*256) % 8
    float z = zsh[o * 8 + n];

    float4 v = reinterpret_cast<const float4*>(T)[i];
    uint4 w;
    w.x = tf32r(v.x * z);
    w.y = tf32r(v.y * z);
    w.z = tf32r(v.z * z);
    w.w = tf32r(v.w * z);
    reinterpret_cast<uint4*>(g_w)[i] = w;
}

// ---------------------------------------------------------------------------
// Kernel 2: C_o = A @ W_o for o in [0,8), tf32 mma.sync m16n8k8.
// Grid: x = M/BM = 64, y = (N/BN)*O = 16. 256 threads = 8 warps (4x2).
// ---------------------------------------------------------------------------
__global__ __launch_bounds__(256)
void gemm_kernel(const float* __restrict__ X, float* __restrict__ out) {
    __shared__ float As[BM * AS_LD];
    __shared__ float Bs[BK * BS_LD];

    const int t    = threadIdx.x;
    const int lane = t & 31;
    const int warp = t >> 5;
    const int gid  = lane >> 2;     // groupID
    const int tig  = lane & 3;      // threadID_in_group
    const int mo   = (warp >> 1) * 32;   // warp m origin (4 warps in m)
    const int no   = (warp & 1) * 64;    // warp n origin (2 warps in n)

    const int m0 = blockIdx.x * BM;
    const int o  = blockIdx.y >> 1;
    const int n0 = (blockIdx.y & 1) * BN;

    const float* Wo = g_w + (size_t)o * (K__ * V__);

    float4 ra[4], rb[4];

    auto loadg = [&](int kt) {
#pragma unroll
        for (int i = 0; i < 4; i++) {
            int j  = t + i * 256;
            int ar = j >> 3, ac = (j & 7) << 2;        // A: 128 rows x 8 float4
            ra[i] = *reinterpret_cast<const float4*>(
                X + (size_t)(m0 + ar) * K__ + kt * BK + ac);
            int bk = j >> 5, bc = (j & 31) << 2;       // B: 32 rows x 32 float4
            rb[i] = *reinterpret_cast<const float4*>(
                Wo + (size_t)(kt * BK + bk) * V__ + n0 + bc);
        }
    };
    auto stos = [&]() {
#pragma unroll
        for (int i = 0; i < 4; i++) {
            int j  = t + i * 256;
            int ar = j >> 3, ac = (j & 7) << 2;
            uint4 a4;
            a4.x = tf32r(ra[i].x); a4.y = tf32r(ra[i].y);
            a4.z = tf32r(ra[i].z); a4.w = tf32r(ra[i].w);
            *reinterpret_cast<uint4*>(&As[ar * AS_LD + ac]) = a4;
            int bk = j >> 5, bc = (j & 31) << 2;
            *reinterpret_cast<float4*>(&Bs[bk * BS_LD + bc]) = rb[i];
        }
    };

    float acc[16][4];
#pragma unroll
    for (int i = 0; i < 16; i++)
#pragma unroll
        for (int j = 0; j < 4; j++) acc[i][j] = 0.0f;

    loadg(0);
    const int KT = K__ / BK;   // 64
    for (int kt = 0; kt < KT; ++kt) {
        stos();
        __syncthreads();
        if (kt + 1 < KT) loadg(kt + 1);   // prefetch overlaps compute

#pragma unroll
        for (int ks = 0; ks < 4; ++ks) {
            const int k0 = ks * 8;
            uint32_t a[2][4], b[8][2];
#pragma unroll
            for (int f = 0; f < 2; f++) {
                int m = mo + f * 16 + gid;
                a[f][0] = __float_as_uint(As[m * AS_LD + k0 + tig]);
                a[f][1] = __float_as_uint(As[(m + 8) * AS_LD + k0 + tig]);
                a[f][2] = __float_as_uint(As[m * AS_LD + k0 + tig + 4]);
                a[f][3] = __float_as_uint(As[(m + 8) * AS_LD + k0 + tig + 4]);
            }
#pragma unroll
            for (int nb = 0; nb < 8; nb++) {
                int c = no + nb * 8 + gid;
                b[nb][0] = __float_as_uint(Bs[(k0 + tig) * BS_LD + c]);
                b[nb][1] = __float_as_uint(Bs[(k0 + tig + 4) * BS_LD + c]);
            }
#pragma unroll
            for (int f = 0; f < 2; f++)
#pragma unroll
                for (int nb = 0; nb < 8; nb++) {
                    float* c = acc[f * 8 + nb];
                    asm volatile(
                        "mma.sync.aligned.m16n8k8.row.col.f32.tf32.tf32.f32 "
                        "{%0,%1,%2,%3}, {%4,%5,%6,%7}, {%8,%9}, {%0,%1,%2,%3};"
                        : "+f"(c[0]), "+f"(c[1]), "+f"(c[2]), "+f"(c[3])
                        : "r"(a[f][0]), "r"(a[f][1]), "r"(a[f][2]), "r"(a[f][3]),
                          "r"(b[nb][0]), "r"(b[nb][1]));
                }
        }
        __syncthreads();
    }

    // Epilogue: out[b][o][v], row stride 8*256 floats per b.
#pragma unroll
    for (int f = 0; f < 2; f++) {
#pragma unroll
        for (int nb = 0; nb < 8; nb++) {
            int m = m0 + mo + f * 16 + gid;
            int c = n0 + no + nb * 8 + 2 * tig;
            float* v = acc[f * 8 + nb];
            *reinterpret_cast<float2*>(
                out + ((size_t)m * O__ + o) * V__ + c) = make_float2(v[0], v[1]);
            *reinterpret_cast<float2*>(
                out + ((size_t)(m + 8) * O__ + o) * V__ + c) = make_float2(v[2], v[3]);
        }
    }
}

// ---------------------------------------------------------------------------
// kernel_launch: identify inputs by element count (defensive vs. ordering),
// then run gate+scale followed by the grouped GEMM. Same stream => ordered.
// ---------------------------------------------------------------------------
extern "C" void kernel_launch(void* const* d_in, const int* in_sizes, int n_in,
                              void* d_out, int out_size) {
    const float* x     = nullptr;   // 16777216 elems
    const float* alpha = nullptr;   // 1
    const float* u     = nullptr;   // 64
    const float* T     = nullptr;   // 4194304
    for (int i = 0; i < n_in; i++) {
        switch (in_sizes[i]) {
            case 16777216: x     = (const float*)d_in[i]; break;
            case 1:        alpha = (const float*)d_in[i]; break;
            case 64:       u     = (const float*)d_in[i]; break;
            case 4194304:  T     = (const float*)d_in[i]; break;
        }
    }
    float* out = (float*)d_out;

    gate_scale_kernel<<<4096, 256>>>(T, alpha, u);
    gemm_kernel<<<dim3(64, 16), 256>>>(x, out);
}

// round 3
// speedup vs baseline: 1.9524x; 1.9524x over previous
#include <cuda_runtime.h>
#include <cuda_fp16.h>
#include <cstdint>

// ===================== problem constants =====================
#define BATCH_ 8192
#define O_     8
#define K_     2048      // N*U
#define V_     256

// ===================== GEMM tiling =====================
#define BM 128
#define BN 256           // one full o per CTA
#define BK 32            // halves per k-chunk
#define KT_ (K_ / BK)    // 64 chunks
#define NSTG 4
#define ROWB 80          // padded smem row: 32 halves = 64B + 16B pad (conflict-free ldmatrix)
#define A_BYTES (BM * ROWB)            // 10240
#define B_BYTES (BN * ROWB)            // 20480
#define STG_BYTES (A_BYTES + B_BYTES)  // 30720
#define SMEM_TOTAL (NSTG * STG_BYTES)  // 122880

// ===================== scratch (device globals; no alloc) =====================
__device__ __half g_xh[(size_t)BATCH_ * K_];   // 32MB fp16 X
__device__ __half g_wh[(size_t)O_ * V_ * K_];  // 8MB gated, transposed fp16 W  [o][v][k]

// ===================== helpers =====================
__device__ __forceinline__ uint32_t smem_u32(const void* p) {
    uint32_t a;
    asm("{ .reg .u64 t; cvta.to.shared.u64 t, %1; cvt.u32.u64 %0, t; }" : "=r"(a) : "l"(p));
    return a;
}
__device__ __forceinline__ void cpa16(uint32_t d, const void* g) {
    asm volatile("cp.async.cg.shared.global [%0], [%1], 16;" :: "r"(d), "l"(g));
}
#define CP_COMMIT() asm volatile("cp.async.commit_group;" ::: "memory")
#define CP_WAIT2()  asm volatile("cp.async.wait_group 2;" ::: "memory")

__device__ __forceinline__ void ldsm4(uint32_t (&r)[4], uint32_t addr) {
    asm volatile("ldmatrix.sync.aligned.m8n8.x4.shared.b16 {%0,%1,%2,%3}, [%4];"
                 : "=r"(r[0]), "=r"(r[1]), "=r"(r[2]), "=r"(r[3]) : "r"(addr));
}
__device__ __forceinline__ void mma16816(float* c, const uint32_t* a,
                                         uint32_t b0, uint32_t b1) {
    asm volatile(
        "mma.sync.aligned.m16n8k16.row.col.f32.f16.f16.f32 "
        "{%0,%1,%2,%3}, {%4,%5,%6,%7}, {%8,%9}, {%0,%1,%2,%3};"
        : "+f"(c[0]), "+f"(c[1]), "+f"(c[2]), "+f"(c[3])
        : "r"(a[0]), "r"(a[1]), "r"(a[2]), "r"(a[3]), "r"(b0), "r"(b1));
}

// ===================== kernel 1: X -> fp16 =====================
__global__ void conv_x(const float4* __restrict__ X) {
    size_t i = (size_t)blockIdx.x * 256 + threadIdx.x;  // 4,194,304 float4s
    float4 v = X[i];
    __half2 h0 = __floats2half2_rn(v.x, v.y);
    __half2 h1 = __floats2half2_rn(v.z, v.w);
    uint2 w;
    w.x = *reinterpret_cast<uint32_t*>(&h0);
    w.y = *reinterpret_cast<uint32_t*>(&h1);
    reinterpret_cast<uint2*>(g_xh)[i] = w;
}

// ===================== kernel 2: gate + transpose + fp16 =====================
// g_wh[o][v][n*256+u] = fp16( T[o][n][u][v] * z[o][n] )
__global__ void gate_tr(const float* __restrict__ T,
                        const float* __restrict__ alpha,
                        const float* __restrict__ u_param) {
    __shared__ float tile[64][65];
    __shared__ float zsh;
    int blk = blockIdx.x;            // 1024 blocks of 256 threads
    int on = blk >> 4;
    int o = on >> 3, n = on & 7;
    int u0 = ((blk >> 2) & 3) * 64;
    int v0 = (blk & 3) * 64;
    int tid = threadIdx.x;

    if (tid == 0) {
        float uu = u_param[o * 8 + n];
        float s = logf(uu) - logf(1.0f - uu) + logf(alpha[0]) / 0.9f;
        s = 1.0f / (1.0f + expf(-s));
        float z = s * 1.2f - 0.1f;
        zsh = fminf(fmaxf(z, 0.0f), 1.0f);
    }
    __syncthreads();

    const float* tb = T + (((size_t)(o * 8 + n) * 256 + u0) * 256 + v0);
#pragma unroll
    for (int i = 0; i < 16; i++) {
        int r = i * 4 + (tid >> 6);
        int c = tid & 63;
        tile[r][c] = tb[(size_t)r * 256 + c];
    }
    __syncthreads();

    float z = zsh;
    __half* wb = g_wh + ((size_t)o * 256 + v0) * 2048 + n * 256 + u0;
#pragma unroll
    for (int i = 0; i < 16; i++) {
        int r = i * 4 + (tid >> 6);   // v-row
        int c = tid & 63;             // u-col (k contiguous)
        wb[(size_t)r * 2048 + c] = __float2half_rn(tile[c][r] * z);
    }
}

// ===================== kernel 3: fp16 pipelined GEMM =====================
// C[b, o*256+v] for one o per CTA: BM=128 x BN=256 x K=2048.
// 512 threads = 16 warps (4m x 4n), warp tile 32x64. 4-stage cp.async pipeline.
__global__ __launch_bounds__(512, 1)
void gemm_fp16(float* __restrict__ out) {
    extern __shared__ char smem[];
    const uint32_t sb = smem_u32(smem);

    const int tid = threadIdx.x, lane = tid & 31, warp = tid >> 5;
    const int m0 = blockIdx.x * BM;
    const int o  = blockIdx.y;

    const __half* Ag = g_xh + (size_t)m0 * K_;
    const __half* Bg = g_wh + (size_t)o * V_ * K_;

    // cp.async mapping: A = 128 rows x 4 x 16B chunks (512 ops), B = 256 rows x 4 (1024 ops)
    const int arow = tid >> 2, ac = tid & 3;
    const __half* asrc = Ag + (size_t)arow * K_ + ac * 8;
    const __half* bsrc = Bg + (size_t)arow * K_ + ac * 8;  // rows 0..127; +128 on 2nd op
    const uint32_t adst = sb + arow * ROWB + ac * 16;
    const uint32_t bdst = sb + A_BYTES + arow * ROWB + ac * 16;

    auto issue = [&](int kt) {
        const uint32_t so = (uint32_t)(kt & 3) * STG_BYTES;
        const __half* a = asrc + kt * BK;
        const __half* b = bsrc + kt * BK;
        cpa16(adst + so, a);
        cpa16(bdst + so, b);
        cpa16(bdst + so + 128 * ROWB, b + (size_t)128 * K_);
    };

    // ldmatrix lane addressing (all non-trans; B stored [v][k] = col-major B)
    const int mo = (warp >> 2) * 32;       // 4 warps in m
    const int no = (warp & 3) * 64;        // 4 warps in n
    uint32_t a_addr[2], b_addr[4];
    {
        const int arl = lane & 15;               // row within m16
        const int akh = (lane >> 4) & 1;         // k-half (bytes +16)
#pragma unroll
        for (int mf = 0; mf < 2; mf++)
            a_addr[mf] = sb + (mo + mf * 16 + arl) * ROWB + akh * 16;
        const int brl = (lane & 7) + ((lane >> 4) & 1) * 8;  // n row
        const int bkh = (lane >> 3) & 1;                      // k-half
#pragma unroll
        for (int p = 0; p < 4; p++)
            b_addr[p] = sb + A_BYTES + (no + p * 16 + brl) * ROWB + bkh * 16;
    }

    float acc[2][8][4];
#pragma unroll
    for (int i = 0; i < 2; i++)
#pragma unroll
        for (int j = 0; j < 8; j++)
#pragma unroll
            for (int k = 0; k < 4; k++) acc[i][j][k] = 0.0f;

    issue(0); CP_COMMIT();
    issue(1); CP_COMMIT();
    issue(2); CP_COMMIT();

    for (int kt = 0; kt < KT_; ++kt) {
        CP_WAIT2();              // group kt complete
        __syncthreads();         // all threads' loads for stage kt visible
        if (kt + 3 < KT_) issue(kt + 3);
        CP_COMMIT();             // commit every iter (empty groups keep count aligned)

        const uint32_t so = (uint32_t)(kt & 3) * STG_BYTES;
#pragma unroll
        for (int ks = 0; ks < 2; ks++) {       // two k16 steps per BK=32
            const uint32_t kb = so + ks * 32;  // 16 halves = 32 bytes
            uint32_t a[2][4], b[4][4];
#pragma unroll
            for (int mf = 0; mf < 2; mf++) ldsm4(a[mf], a_addr[mf] + kb);
#pragma unroll
            for (int p = 0; p < 4; p++) ldsm4(b[p], b_addr[p] + kb);
#pragma unroll
            for (int mf = 0; mf < 2; mf++)
#pragma unroll
                for (int p = 0; p < 4; p++) {
                    mma16816(acc[mf][2 * p],     a[mf], b[p][0], b[p][1]);
                    mma16816(acc[mf][2 * p + 1], a[mf], b[p][2], b[p][3]);
                }
        }
    }

    // epilogue: out[b][o][v]
    const int gid = lane >> 2, tig = lane & 3;
#pragma unroll
    for (int mf = 0; mf < 2; mf++) {
        const int brow = m0 + mo + mf * 16 + gid;
#pragma unroll
        for (int nb = 0; nb < 8; nb++) {
            const int v = no + nb * 8 + tig * 2;
            float* c = acc[mf][nb];
            *reinterpret_cast<float2*>(
                out + ((size_t)brow * O_ + o) * V_ + v) = make_float2(c[0], c[1]);
            *reinterpret_cast<float2*>(
                out + ((size_t)(brow + 8) * O_ + o) * V_ + v) = make_float2(c[2], c[3]);
        }
    }
}

// ===================== host =====================
extern "C" void kernel_launch(void* const* d_in, const int* in_sizes, int n_in,
                              void* d_out, int out_size) {
    const float* x = nullptr, *alpha = nullptr, *u = nullptr, *T = nullptr;
    for (int i = 0; i < n_in; i++) {
        switch (in_sizes[i]) {
            case 16777216: x     = (const float*)d_in[i]; break;
            case 1:        alpha = (const float*)d_in[i]; break;
            case 64:       u     = (const float*)d_in[i]; break;
            case 4194304:  T     = (const float*)d_in[i]; break;
        }
    }
    if (!x || !alpha || !u || !T) return;
    float* out = (float*)d_out;

    static bool attr_set = false;
    if (!attr_set) {
        cudaFuncSetAttribute(gemm_fp16, cudaFuncAttributeMaxDynamicSharedMemorySize,
                             SMEM_TOTAL);
        attr_set = true;
    }

    conv_x<<<16384, 256>>>(reinterpret_cast<const float4*>(x));
    gate_tr<<<1024, 256>>>(T, alpha, u);
    gemm_fp16<<<dim3(64, 8), 512, SMEM_TOTAL>>>(out);
}

// round 4
// speedup vs baseline: 8.9525x; 4.5853x over previous
#include <cuda_runtime.h>
#include <cuda_fp16.h>
#include <cstdint>

// ===================== problem constants =====================
#define BATCH_ 8192
#define O_     8
#define K_     2048      // N*U
#define V_     256

// ===================== GEMM tiling =====================
#define BM 128
#define BN 128
#define BK 32            // halves per k-chunk
#define NSTG 4
#define ROWB 80          // padded smem row: 32 halves + 16B pad
#define A_BYTES (BM * ROWB)            // 10240
#define B_BYTES (BN * ROWB)            // 10240
#define STG_BYTES (A_BYTES + B_BYTES)  // 20480
#define SMEM_TOTAL (NSTG * STG_BYTES)  // 81920

// ===================== scratch (device globals; no alloc) =====================
__device__ __half g_xh[(size_t)BATCH_ * K_];   // 32MB fp16 X
__device__ __half g_wh[(size_t)O_ * V_ * K_];  // 8MB gated, transposed fp16 W [o][v][k]
__device__ int    g_nlist[O_ * 8];             // compacted active-n lists
__device__ int    g_ncnt[O_];                  // active-n counts

// ===================== helpers =====================
__device__ __forceinline__ uint32_t smem_u32(const void* p) {
    uint32_t a;
    asm("{ .reg .u64 t; cvta.to.shared.u64 t, %1; cvt.u32.u64 %0, t; }" : "=r"(a) : "l"(p));
    return a;
}
__device__ __forceinline__ void cpa16(uint32_t d, const void* g) {
    asm volatile("cp.async.cg.shared.global [%0], [%1], 16;" :: "r"(d), "l"(g));
}
#define CP_COMMIT() asm volatile("cp.async.commit_group;" ::: "memory")
#define CP_WAIT2()  asm volatile("cp.async.wait_group 2;" ::: "memory")

__device__ __forceinline__ void ldsm4(uint32_t (&r)[4], uint32_t addr) {
    asm volatile("ldmatrix.sync.aligned.m8n8.x4.shared.b16 {%0,%1,%2,%3}, [%4];"
                 : "=r"(r[0]), "=r"(r[1]), "=r"(r[2]), "=r"(r[3]) : "r"(addr));
}
__device__ __forceinline__ void mma16816(float* c, const uint32_t* a,
                                         uint32_t b0, uint32_t b1) {
    asm volatile(
        "mma.sync.aligned.m16n8k16.row.col.f32.f16.f16.f32 "
        "{%0,%1,%2,%3}, {%4,%5,%6,%7}, {%8,%9}, {%0,%1,%2,%3};"
        : "+f"(c[0]), "+f"(c[1]), "+f"(c[2]), "+f"(c[3])
        : "r"(a[0]), "r"(a[1]), "r"(a[2]), "r"(a[3]), "r"(b0), "r"(b1));
}

__device__ __forceinline__ float gate_z(const float* u_param, const float* alpha, int idx) {
    float uu = u_param[idx];
    float s = logf(uu) - logf(1.0f - uu) + logf(alpha[0]) / 0.9f;
    s = 1.0f / (1.0f + expf(-s));
    float z = s * 1.2f - 0.1f;
    return fminf(fmaxf(z, 0.0f), 1.0f);
}

// ===================== fused prepass =====================
// blocks [0, 16384): X -> fp16            (grid-stride-free, 1 float4/thread)
// blocks [16384, 17408): gate + transpose + fp16 W; block 16384 also builds lists.
__global__ void prep(const float4* __restrict__ X,
                     const float* __restrict__ T,
                     const float* __restrict__ alpha,
                     const float* __restrict__ u_param) {
    int tid = threadIdx.x;
    if (blockIdx.x < 16384) {
        size_t i = (size_t)blockIdx.x * 256 + tid;
        float4 v = X[i];
        __half2 h0 = __floats2half2_rn(v.x, v.y);
        __half2 h1 = __floats2half2_rn(v.z, v.w);
        uint2 w;
        w.x = *reinterpret_cast<uint32_t*>(&h0);
        w.y = *reinterpret_cast<uint32_t*>(&h1);
        reinterpret_cast<uint2*>(g_xh)[i] = w;
        return;
    }

    __shared__ float tile[64][65];
    __shared__ float zsh;
    int blk = blockIdx.x - 16384;     // 0..1023
    int on = blk >> 4;
    int o = on >> 3, n = on & 7;
    int u0 = ((blk >> 2) & 3) * 64;
    int v0 = (blk & 3) * 64;

    if (blk == 0 && tid < 8) {        // build compacted active-n lists
        int cnt = 0;
        for (int nn = 0; nn < 8; nn++) {
            if (gate_z(u_param, alpha, tid * 8 + nn) > 0.0f)
                g_nlist[tid * 8 + cnt++] = nn;
        }
        g_ncnt[tid] = cnt;
    }
    if (tid == 0) zsh = gate_z(u_param, alpha, o * 8 + n);
    __syncthreads();
    float z = zsh;
    if (z == 0.0f) return;            // closed gate: W block never read

    const float* tb = T + (((size_t)(o * 8 + n) * 256 + u0) * 256 + v0);
#pragma unroll
    for (int i = 0; i < 16; i++) {
        int r = i * 4 + (tid >> 6);
        int c = tid & 63;
        tile[r][c] = tb[(size_t)r * 256 + c];
    }
    __syncthreads();

    __half* wb = g_wh + ((size_t)o * 256 + v0) * 2048 + n * 256 + u0;
#pragma unroll
    for (int i = 0; i < 16; i++) {
        int r = i * 4 + (tid >> 6);   // v-row
        int c = tid & 63;             // u-col (k contiguous)
        wb[(size_t)r * 2048 + c] = __float2half_rn(tile[c][r] * z);
    }
}

// ===================== fp16 pipelined GEMM with gate skipping =====================
// Tile: BM=128 x BN=128; grid (64, 16): y -> (o, n-half). 256 threads = 8 warps (4m x 2n).
__global__ __launch_bounds__(256)
void gemm_fp16(float* __restrict__ out) {
    extern __shared__ char smem[];
    const uint32_t sb = smem_u32(smem);
    __shared__ int nlist_s[8];
    __shared__ int cnt_s;

    const int tid = threadIdx.x, lane = tid & 31, warp = tid >> 5;
    const int m0 = blockIdx.x * BM;
    const int o  = blockIdx.y >> 1;
    const int n0 = (blockIdx.y & 1) * BN;

    if (tid < 8) nlist_s[tid] = g_nlist[o * 8 + tid];
    if (tid == 8) cnt_s = g_ncnt[o];
    __syncthreads();
    const int chunks = cnt_s * 8;     // 8 x BK=32 chunks per active n

    const __half* Ag = g_xh + (size_t)m0 * K_;
    const __half* Bg = g_wh + ((size_t)o * V_ + n0) * K_;

    // cp.async mapping: 2 A ops + 2 B ops per thread (128 rows x 4 x 16B each)
    const int i0 = tid * 2;                       // 0..510 step 2
    const int r0 = i0 >> 2, c0 = i0 & 3;          // first chunk
    const int r1 = (i0 + 1) >> 2, c1 = (i0 + 1) & 3;

    auto issue = [&](int c) {
        const uint32_t so = (uint32_t)(c & 3) * STG_BYTES;
        const int k0 = (nlist_s[c >> 3] << 8) + ((c & 7) << 5);
        cpa16(sb + so + r0 * ROWB + c0 * 16,           Ag + (size_t)r0 * K_ + k0 + c0 * 8);
        cpa16(sb + so + r1 * ROWB + c1 * 16,           Ag + (size_t)r1 * K_ + k0 + c1 * 8);
        cpa16(sb + so + A_BYTES + r0 * ROWB + c0 * 16, Bg + (size_t)r0 * K_ + k0 + c0 * 8);
        cpa16(sb + so + A_BYTES + r1 * ROWB + c1 * 16, Bg + (size_t)r1 * K_ + k0 + c1 * 8);
    };

    // ldmatrix lane addressing (non-trans; B stored [v][k])
    const int mo = (warp >> 1) * 32;   // 4 warps in m
    const int no = (warp & 1) * 64;    // 2 warps in n
    uint32_t a_addr[2], b_addr[4];
    {
        const int arl = lane & 15;
        const int akh = (lane >> 4) & 1;
#pragma unroll
        for (int mf = 0; mf < 2; mf++)
            a_addr[mf] = sb + (mo + mf * 16 + arl) * ROWB + akh * 16;
        const int brl = (lane & 7) + ((lane >> 4) & 1) * 8;
        const int bkh = (lane >> 3) & 1;
#pragma unroll
        for (int p = 0; p < 4; p++)
            b_addr[p] = sb + A_BYTES + (no + p * 16 + brl) * ROWB + bkh * 16;
    }

    float acc[2][8][4];
#pragma unroll
    for (int i = 0; i < 2; i++)
#pragma unroll
        for (int j = 0; j < 8; j++)
#pragma unroll
            for (int k = 0; k < 4; k++) acc[i][j][k] = 0.0f;

#pragma unroll
    for (int p = 0; p < 3; p++) {
        if (p < chunks) issue(p);
        CP_COMMIT();
    }

    for (int c = 0; c < chunks; ++c) {
        CP_WAIT2();
        __syncthreads();
        if (c + 3 < chunks) issue(c + 3);
        CP_COMMIT();

        const uint32_t so = (uint32_t)(c & 3) * STG_BYTES;
#pragma unroll
        for (int ks = 0; ks < 2; ks++) {
            const uint32_t kb = so + ks * 32;
            uint32_t a[2][4], b[4][4];
#pragma unroll
            for (int mf = 0; mf < 2; mf++) ldsm4(a[mf], a_addr[mf] + kb);
#pragma unroll
            for (int p = 0; p < 4; p++) ldsm4(b[p], b_addr[p] + kb);
#pragma unroll
            for (int mf = 0; mf < 2; mf++)
#pragma unroll
                for (int p = 0; p < 4; p++) {
                    mma16816(acc[mf][2 * p],     a[mf], b[p][0], b[p][1]);
                    mma16816(acc[mf][2 * p + 1], a[mf], b[p][2], b[p][3]);
                }
        }
        __syncthreads();
    }

    // epilogue: out[b][o][v]
    const int gid = lane >> 2, tig = lane & 3;
#pragma unroll
    for (int mf = 0; mf < 2; mf++) {
        const int brow = m0 + mo + mf * 16 + gid;
#pragma unroll
        for (int nb = 0; nb < 8; nb++) {
            const int v = n0 + no + nb * 8 + tig * 2;
            float* c = acc[mf][nb];
            *reinterpret_cast<float2*>(
                out + ((size_t)brow * O_ + o) * V_ + v) = make_float2(c[0], c[1]);
            *reinterpret_cast<float2*>(
                out + ((size_t)(brow + 8) * O_ + o) * V_ + v) = make_float2(c[2], c[3]);
        }
    }
}

// ===================== host =====================
extern "C" void kernel_launch(void* const* d_in, const int* in_sizes, int n_in,
                              void* d_out, int out_size) {
    const float* x = nullptr, *alpha = nullptr, *u = nullptr, *T = nullptr;
    for (int i = 0; i < n_in; i++) {
        switch (in_sizes[i]) {
            case 16777216: x     = (const float*)d_in[i]; break;
            case 1:        alpha = (const float*)d_in[i]; break;
            case 64:       u     = (const float*)d_in[i]; break;
            case 4194304:  T     = (const float*)d_in[i]; break;
        }
    }
    if (!x || !alpha || !u || !T) return;
    float* out = (float*)d_out;

    static bool attr_set = false;
    if (!attr_set) {
        cudaFuncSetAttribute(gemm_fp16, cudaFuncAttributeMaxDynamicSharedMemorySize,
                             SMEM_TOTAL);
        attr_set = true;
    }

    prep<<<16384 + 1024, 256>>>(reinterpret_cast<const float4*>(x), T, alpha, u);
    gemm_fp16<<<dim3(64, 16), 256, SMEM_TOTAL>>>(out);
}